// round 2
// baseline (speedup 1.0000x reference)
#include <cuda_runtime.h>
#include <math.h>
#include <cstdint>

#define LSEQ   2048
#define NB     4
#define DMODEL 1024
#define NH     16
#define HSIZE  64
#define MROWS  (NB*LSEQ)   // 8192

// Scratch (allocation-free rule: __device__ globals)
__device__ float g_Q[(size_t)NB*NH*LSEQ*HSIZE];
__device__ float g_K[(size_t)NB*NH*LSEQ*HSIZE];
__device__ float g_V[(size_t)NB*NH*LSEQ*HSIZE];
__device__ float g_Y[(size_t)MROWS*DMODEL];

// ---------------------------------------------------------------------------
// Kernel 1: qkv = x @ W_attn + b_attn, scattered into head-major Q/K/V.
// 128x128 tile, BK=8, 256 threads, 8x8 microtile, double-buffered smem.
// ---------------------------------------------------------------------------
__global__ __launch_bounds__(256, 2) void gemm_qkv_kernel(
    const float* __restrict__ X, const float* __restrict__ W,
    const float* __restrict__ bias)
{
    __shared__ float As[2][8][128];
    __shared__ float Bs[2][8][128];
    const int tid  = threadIdx.x;
    const int m0   = blockIdx.y * 128;
    const int n0   = blockIdx.x * 128;
    const int trow = tid >> 4;          // 0..15
    const int tcol = tid & 15;          // 0..15
    const int aRow = tid >> 1;          // 0..127
    const int aCol = (tid & 1) << 2;    // 0 or 4
    const int bRow = tid >> 5;          // 0..7
    const int bCol = (tid & 31) << 2;   // 0..124

    const float* Ap = X + (size_t)(m0 + aRow) * DMODEL + aCol;
    const float* Bp = W + (size_t)bRow * 3072 + n0 + bCol;

    float acc[8][8];
    #pragma unroll
    for (int i = 0; i < 8; i++)
        #pragma unroll
        for (int j = 0; j < 8; j++) acc[i][j] = 0.f;

    // prologue: tile 0 -> buffer 0
    {
        float4 av = *(const float4*)(Ap);
        float4 bv = *(const float4*)(Bp);
        As[0][aCol+0][aRow] = av.x;
        As[0][aCol+1][aRow] = av.y;
        As[0][aCol+2][aRow] = av.z;
        As[0][aCol+3][aRow] = av.w;
        *(float4*)&Bs[0][bRow][bCol] = bv;
    }
    __syncthreads();

    const int NT = DMODEL / 8;   // 128
    for (int t = 0; t < NT; t++) {
        const int buf = t & 1;
        float4 anext, bnext;
        if (t + 1 < NT) {
            anext = *(const float4*)(Ap + (t+1)*8);
            bnext = *(const float4*)(Bp + (size_t)(t+1)*8*3072);
        }
        #pragma unroll
        for (int kk = 0; kk < 8; kk++) {
            float a[8], b[8];
            *(float4*)&a[0] = *(const float4*)&As[buf][kk][trow*8];
            *(float4*)&a[4] = *(const float4*)&As[buf][kk][trow*8 + 4];
            *(float4*)&b[0] = *(const float4*)&Bs[buf][kk][tcol*8];
            *(float4*)&b[4] = *(const float4*)&Bs[buf][kk][tcol*8 + 4];
            #pragma unroll
            for (int i = 0; i < 8; i++)
                #pragma unroll
                for (int j = 0; j < 8; j++)
                    acc[i][j] = fmaf(a[i], b[j], acc[i][j]);
        }
        if (t + 1 < NT) {
            const int nb = buf ^ 1;
            As[nb][aCol+0][aRow] = anext.x;
            As[nb][aCol+1][aRow] = anext.y;
            As[nb][aCol+2][aRow] = anext.z;
            As[nb][aCol+3][aRow] = anext.w;
            *(float4*)&Bs[nb][bRow][bCol] = bnext;
        }
        __syncthreads();
    }

    // Epilogue: scatter into head-major Q/K/V.  Tile lies entirely inside one
    // of the q/k/v chunks because 1024 % 128 == 0.
    const int chunk = n0 >> 10;
    float* dst = (chunk == 0) ? g_Q : (chunk == 1) ? g_K : g_V;
    #pragma unroll
    for (int i = 0; i < 8; i++) {
        const int m  = m0 + trow*8 + i;
        const int bb = m >> 11;
        const int l  = m & (LSEQ - 1);
        #pragma unroll
        for (int j4 = 0; j4 < 8; j4 += 4) {
            const int n = n0 + tcol*8 + j4;
            const int d = n - (chunk << 10);
            const int h = d >> 6;
            const int e = d & 63;
            float4 ov;
            ov.x = acc[i][j4+0] + bias[n+0];
            ov.y = acc[i][j4+1] + bias[n+1];
            ov.z = acc[i][j4+2] + bias[n+2];
            ov.w = acc[i][j4+3] + bias[n+3];
            *(float4*)&dst[((((size_t)bb*NH + h)*LSEQ + l) << 6) + e] = ov;
        }
    }
}

// ---------------------------------------------------------------------------
// Kernel 2: fused causal flash attention with relative-position band.
// Srel[i,j] = q_i . Er[L-1-i+j]  (j <= i), fused as  q . (k + er).
// grid = (32 q-tiles, 64 batch*head), 256 threads, 4x4 microtile.
// ---------------------------------------------------------------------------
__global__ __launch_bounds__(256) void attn_kernel(const float* __restrict__ Er)
{
    extern __shared__ float sm[];
    float* qT  = sm;            // [64][68]  qT[d][i]
    float* kT  = sm + 4352;     // [64][68]  kT[d][j]
    float* vS  = sm + 8704;     // [64][68]  vS[j][e]
    float* pT  = sm + 13056;    // [64][68]  pT[j][i]
    float* erS = sm + 17408;    // [64][132] erS[d][m], m in [0,127]

    const int tid = threadIdx.x;
    const int tx  = tid & 15;   // key / hs-col group
    const int ty  = tid >> 4;   // query-row group
    const int qt  = blockIdx.x;
    const int bh  = blockIdx.y;
    const int i0  = qt << 6;

    const float* Qb = g_Q + (size_t)bh * LSEQ * HSIZE;
    const float* Kb = g_K + (size_t)bh * LSEQ * HSIZE;
    const float* Vb = g_V + (size_t)bh * LSEQ * HSIZE;

    // load q tile transposed: qT[d][i]
    #pragma unroll
    for (int r = 0; r < 4; r++) {
        int idx = tid + (r << 8);
        int row = idx >> 4;
        int f   = (idx & 15) << 2;
        float4 v = *(const float4*)(Qb + (size_t)(i0 + row) * HSIZE + f);
        qT[(f+0)*68 + row] = v.x;
        qT[(f+1)*68 + row] = v.y;
        qT[(f+2)*68 + row] = v.z;
        qT[(f+3)*68 + row] = v.w;
    }

    float mrow[4], lrow[4], o[4][4];
    #pragma unroll
    for (int a = 0; a < 4; a++) {
        mrow[a] = -INFINITY;
        lrow[a] = 0.f;
        #pragma unroll
        for (int e = 0; e < 4; e++) o[a][e] = 0.f;
    }

    // er local index for S[a][b]:  63 + (tx*4+b) - (ty*4+a) = erBase + 3 + b - a
    const int erBase = 60 + ((tx - ty) << 2);   // in [0,120], aligned to 4

    for (int kt = 0; kt <= qt; kt++) {
        const int j0 = kt << 6;
        __syncthreads();   // previous iteration's pT/vS consumed

        // load K tile transposed + V tile natural
        #pragma unroll
        for (int r = 0; r < 4; r++) {
            int idx = tid + (r << 8);
            int row = idx >> 4;
            int f   = (idx & 15) << 2;
            float4 kv = *(const float4*)(Kb + (size_t)(j0 + row) * HSIZE + f);
            kT[(f+0)*68 + row] = kv.x;
            kT[(f+1)*68 + row] = kv.y;
            kT[(f+2)*68 + row] = kv.z;
            kT[(f+3)*68 + row] = kv.w;
            float4 vv = *(const float4*)(Vb + (size_t)(j0 + row) * HSIZE + f);
            *(float4*)&vS[row*68 + f] = vv;
        }
        // load Er band transposed: erS[d][m], global row = m_lo + m
        const int m_lo = LSEQ - 64 - i0 + j0;   // >= 0 always
        #pragma unroll
        for (int r = 0; r < 8; r++) {
            int idx = tid + (r << 8);
            int mm  = idx >> 4;           // 0..127
            int f   = (idx & 15) << 2;
            int mg  = m_lo + mm;
            float4 ev = make_float4(0.f, 0.f, 0.f, 0.f);
            if (mg < LSEQ)
                ev = *(const float4*)(Er + (size_t)mg * HSIZE + f);
            erS[(f+0)*132 + mm] = ev.x;
            erS[(f+1)*132 + mm] = ev.y;
            erS[(f+2)*132 + mm] = ev.z;
            erS[(f+3)*132 + mm] = ev.w;
        }
        __syncthreads();

        // S = q.(k + er)
        float s[4][4];
        #pragma unroll
        for (int a = 0; a < 4; a++)
            #pragma unroll
            for (int b = 0; b < 4; b++) s[a][b] = 0.f;

        #pragma unroll 8
        for (int d = 0; d < 64; d++) {
            float4 qv = *(const float4*)&qT[d*68 + (ty << 2)];
            float4 kv = *(const float4*)&kT[d*68 + (tx << 2)];
            float4 e0 = *(const float4*)&erS[d*132 + erBase];
            float4 e1 = *(const float4*)&erS[d*132 + erBase + 4];
            float qa[4]  = {qv.x, qv.y, qv.z, qv.w};
            float ka[4]  = {kv.x, kv.y, kv.z, kv.w};
            float er8[8] = {e0.x, e0.y, e0.z, e0.w, e1.x, e1.y, e1.z, e1.w};
            #pragma unroll
            for (int a = 0; a < 4; a++)
                #pragma unroll
                for (int b = 0; b < 4; b++)
                    s[a][b] = fmaf(qa[a], ka[b] + er8[3 + b - a], s[a][b]);
        }

        // scale + causal mask (only the diagonal tile has masked entries)
        const bool diag = (kt == qt);
        #pragma unroll
        for (int a = 0; a < 4; a++)
            #pragma unroll
            for (int b = 0; b < 4; b++) {
                float sv = s[a][b] * 0.125f;   // 1/sqrt(64)
                if (diag && ((tx << 2) + b) > ((ty << 2) + a)) sv = -INFINITY;
                s[a][b] = sv;
            }

        // online softmax, row stats reduced over the 16 tx lanes
        #pragma unroll
        for (int a = 0; a < 4; a++) {
            float mt = fmaxf(fmaxf(s[a][0], s[a][1]), fmaxf(s[a][2], s[a][3]));
            #pragma unroll
            for (int off = 8; off; off >>= 1)
                mt = fmaxf(mt, __shfl_xor_sync(0xffffffffu, mt, off));
            float mnew  = fmaxf(mrow[a], mt);
            float alpha = __expf(mrow[a] - mnew);
            mrow[a] = mnew;
            float ps = 0.f;
            #pragma unroll
            for (int b = 0; b < 4; b++) {
                float p = __expf(s[a][b] - mnew);
                s[a][b] = p;
                ps += p;
            }
            #pragma unroll
            for (int off = 8; off; off >>= 1)
                ps += __shfl_xor_sync(0xffffffffu, ps, off);
            lrow[a] = lrow[a] * alpha + ps;
            #pragma unroll
            for (int e = 0; e < 4; e++) o[a][e] *= alpha;
        }

        // P -> smem transposed: pT[j][i]
        #pragma unroll
        for (int b = 0; b < 4; b++) {
            float4 pv = make_float4(s[0][b], s[1][b], s[2][b], s[3][b]);
            *(float4*)&pT[((tx << 2) + b)*68 + (ty << 2)] = pv;
        }
        __syncthreads();

        // O += P @ V
        #pragma unroll 8
        for (int j = 0; j < 64; j++) {
            float4 pv = *(const float4*)&pT[j*68 + (ty << 2)];
            float4 vv = *(const float4*)&vS[j*68 + (tx << 2)];
            float pr[4] = {pv.x, pv.y, pv.z, pv.w};
            float vr[4] = {vv.x, vv.y, vv.z, vv.w};
            #pragma unroll
            for (int a = 0; a < 4; a++)
                #pragma unroll
                for (int e = 0; e < 4; e++)
                    o[a][e] = fmaf(pr[a], vr[e], o[a][e]);
        }
    }

    // epilogue: y[b, l, h*64+e] = o / l
    const int bb = bh >> 4;
    const int h  = bh & 15;
    #pragma unroll
    for (int a = 0; a < 4; a++) {
        float inv = 1.f / lrow[a];
        int row = i0 + (ty << 2) + a;
        float4 ov = make_float4(o[a][0]*inv, o[a][1]*inv, o[a][2]*inv, o[a][3]*inv);
        *(float4*)&g_Y[((size_t)bb*LSEQ + row)*DMODEL + (h << 6) + (tx << 2)] = ov;
    }
}

// ---------------------------------------------------------------------------
// Kernel 3: out = g_Y @ W_proj + b_proj  (double-buffered like kernel 1)
// ---------------------------------------------------------------------------
__global__ __launch_bounds__(256, 2) void gemm_proj_kernel(
    const float* __restrict__ W, const float* __restrict__ bias,
    float* __restrict__ out)
{
    __shared__ float As[2][8][128];
    __shared__ float Bs[2][8][128];
    const int tid  = threadIdx.x;
    const int m0   = blockIdx.y * 128;
    const int n0   = blockIdx.x * 128;
    const int trow = tid >> 4;
    const int tcol = tid & 15;
    const int aRow = tid >> 1;
    const int aCol = (tid & 1) << 2;
    const int bRow = tid >> 5;
    const int bCol = (tid & 31) << 2;

    const float* Ap = g_Y + (size_t)(m0 + aRow) * DMODEL + aCol;
    const float* Bp = W + (size_t)bRow * DMODEL + n0 + bCol;

    float acc[8][8];
    #pragma unroll
    for (int i = 0; i < 8; i++)
        #pragma unroll
        for (int j = 0; j < 8; j++) acc[i][j] = 0.f;

    {
        float4 av = *(const float4*)(Ap);
        float4 bv = *(const float4*)(Bp);
        As[0][aCol+0][aRow] = av.x;
        As[0][aCol+1][aRow] = av.y;
        As[0][aCol+2][aRow] = av.z;
        As[0][aCol+3][aRow] = av.w;
        *(float4*)&Bs[0][bRow][bCol] = bv;
    }
    __syncthreads();

    const int NT = DMODEL / 8;   // 128
    for (int t = 0; t < NT; t++) {
        const int buf = t & 1;
        float4 anext, bnext;
        if (t + 1 < NT) {
            anext = *(const float4*)(Ap + (t+1)*8);
            bnext = *(const float4*)(Bp + (size_t)(t+1)*8*DMODEL);
        }
        #pragma unroll
        for (int kk = 0; kk < 8; kk++) {
            float a[8], b[8];
            *(float4*)&a[0] = *(const float4*)&As[buf][kk][trow*8];
            *(float4*)&a[4] = *(const float4*)&As[buf][kk][trow*8 + 4];
            *(float4*)&b[0] = *(const float4*)&Bs[buf][kk][tcol*8];
            *(float4*)&b[4] = *(const float4*)&Bs[buf][kk][tcol*8 + 4];
            #pragma unroll
            for (int i = 0; i < 8; i++)
                #pragma unroll
                for (int j = 0; j < 8; j++)
                    acc[i][j] = fmaf(a[i], b[j], acc[i][j]);
        }
        if (t + 1 < NT) {
            const int nb = buf ^ 1;
            As[nb][aCol+0][aRow] = anext.x;
            As[nb][aCol+1][aRow] = anext.y;
            As[nb][aCol+2][aRow] = anext.z;
            As[nb][aCol+3][aRow] = anext.w;
            *(float4*)&Bs[nb][bRow][bCol] = bnext;
        }
        __syncthreads();
    }

    #pragma unroll
    for (int i = 0; i < 8; i++) {
        const int m = m0 + trow*8 + i;
        #pragma unroll
        for (int j4 = 0; j4 < 8; j4 += 4) {
            const int n = n0 + tcol*8 + j4;
            float4 ov;
            ov.x = acc[i][j4+0] + bias[n+0];
            ov.y = acc[i][j4+1] + bias[n+1];
            ov.z = acc[i][j4+2] + bias[n+2];
            ov.w = acc[i][j4+3] + bias[n+3];
            *(float4*)&out[(size_t)m * DMODEL + n] = ov;
        }
    }
}

// ---------------------------------------------------------------------------
extern "C" void kernel_launch(void* const* d_in, const int* in_sizes, int n_in,
                              void* d_out, int out_size)
{
    const float* x      = (const float*)d_in[0];
    const float* W_attn = (const float*)d_in[1];
    const float* b_attn = (const float*)d_in[2];
    const float* W_proj = (const float*)d_in[3];
    const float* b_proj = (const float*)d_in[4];
    const float* Er     = (const float*)d_in[5];
    float* out = (float*)d_out;

    (void)in_sizes; (void)n_in; (void)out_size;

    cudaFuncSetAttribute(attn_kernel,
                         cudaFuncAttributeMaxDynamicSharedMemorySize, 103424);

    gemm_qkv_kernel<<<dim3(24, 64), 256>>>(x, W_attn, b_attn);
    attn_kernel<<<dim3(32, 64), 256, 103424>>>(Er);
    gemm_proj_kernel<<<dim3(8, 64), 256>>>(W_proj, b_proj, out);
}